// round 3
// baseline (speedup 1.0000x reference)
#include <cuda_runtime.h>

// Problem shape
#define B_   4
#define H_   16
#define S_   2048
#define HD_  64
#define D_   1024
#define MTOT (B_ * S_)   // 8192 rows
#define N3   (3 * D_)    // 3072

// Scratch (static device globals — no runtime allocation)
__device__ float g_q[B_ * H_ * S_ * HD_];
__device__ float g_k[B_ * H_ * S_ * HD_];
__device__ float g_v[B_ * H_ * S_ * HD_];
__device__ float g_ctx[MTOT * D_];

// ---------------------------------------------------------------------------
// Kernel 1: QKV projection.  C[m][n] = sum_k X[m][k] * W[n][k] + bias[n],
// scattered into g_q/g_k/g_v with layout [B][H][S][HD].
// 128x128x8 tiled SGEMM, 256 threads, 8x8 per thread.
// ---------------------------------------------------------------------------
__global__ __launch_bounds__(256, 2)
void qkv_gemm_kernel(const float* __restrict__ X,
                     const float* __restrict__ W,
                     const float* __restrict__ bias) {
    __shared__ __align__(16) float As[8][128];
    __shared__ __align__(16) float Bs[8][128];

    const int tid = threadIdx.x;
    const int tx  = tid & 15;          // 0..15 -> N direction
    const int ty  = tid >> 4;          // 0..15 -> M direction
    const int M0  = blockIdx.y * 128;
    const int N0  = blockIdx.x * 128;

    // gmem load mapping: each thread loads one float4 of A and one of B per k-step
    const int lrow = tid >> 1;          // 0..127
    const int lcol = (tid & 1) * 4;     // 0 or 4
    const float* Aptr = X + (M0 + lrow) * D_ + lcol;
    const float* Bptr = W + (N0 + lrow) * D_ + lcol;

    float acc[8][8];
#pragma unroll
    for (int i = 0; i < 8; ++i)
#pragma unroll
        for (int j = 0; j < 8; ++j) acc[i][j] = 0.f;

    for (int k0 = 0; k0 < D_; k0 += 8) {
        float4 a = *(const float4*)(Aptr + k0);
        float4 b = *(const float4*)(Bptr + k0);
        As[lcol + 0][lrow] = a.x; As[lcol + 1][lrow] = a.y;
        As[lcol + 2][lrow] = a.z; As[lcol + 3][lrow] = a.w;
        Bs[lcol + 0][lrow] = b.x; Bs[lcol + 1][lrow] = b.y;
        Bs[lcol + 2][lrow] = b.z; Bs[lcol + 3][lrow] = b.w;
        __syncthreads();

#pragma unroll
        for (int k = 0; k < 8; ++k) {
            float4 a0 = *(const float4*)&As[k][ty * 8];
            float4 a1 = *(const float4*)&As[k][ty * 8 + 4];
            float4 b0 = *(const float4*)&Bs[k][tx * 8];
            float4 b1 = *(const float4*)&Bs[k][tx * 8 + 4];
            float ar[8] = {a0.x, a0.y, a0.z, a0.w, a1.x, a1.y, a1.z, a1.w};
            float br[8] = {b0.x, b0.y, b0.z, b0.w, b1.x, b1.y, b1.z, b1.w};
#pragma unroll
            for (int i = 0; i < 8; ++i)
#pragma unroll
                for (int j = 0; j < 8; ++j)
                    acc[i][j] = fmaf(ar[i], br[j], acc[i][j]);
        }
        __syncthreads();
    }

    // Epilogue: bias + scatter.  This thread's 8 columns are n0..n0+7; since
    // n0 % 8 == 0 and head width (64) and the q/k/v 1024 boundaries are both
    // multiples of 8, all 8 columns share the same (tensor, head).
    const int n0 = N0 + tx * 8;
    const int t  = n0 / D_;            // 0=q, 1=k, 2=v
    const int d  = n0 % D_;
    const int h  = d >> 6;
    const int dd = d & 63;
    float* dstbase = (t == 0) ? g_q : (t == 1) ? g_k : g_v;

    float bv[8];
#pragma unroll
    for (int j = 0; j < 8; ++j) bv[j] = bias[n0 + j];

#pragma unroll
    for (int i = 0; i < 8; ++i) {
        const int m  = M0 + ty * 8 + i;
        const int bb = m >> 11;            // / 2048
        const int s  = m & 2047;
        float* dst = dstbase + (((bb * H_ + h) * S_ + s) * HD_ + dd);
        float4 v0 = {acc[i][0] + bv[0], acc[i][1] + bv[1],
                     acc[i][2] + bv[2], acc[i][3] + bv[3]};
        float4 v1 = {acc[i][4] + bv[4], acc[i][5] + bv[5],
                     acc[i][6] + bv[6], acc[i][7] + bv[7]};
        *(float4*)(dst)     = v0;
        *(float4*)(dst + 4) = v1;
    }
}

// ---------------------------------------------------------------------------
// Kernel 2: Flash attention (fp32, online softmax in log2 domain).
// One thread owns one query row (q and acc in registers), K/V tiles in smem.
// Grid: (S/128, H, B), 128 threads.
// ---------------------------------------------------------------------------
__global__ __launch_bounds__(128)
void flash_attn_kernel() {
    const int b   = blockIdx.z;
    const int h   = blockIdx.y;
    const int tid = threadIdx.x;
    const int row = blockIdx.x * 128 + tid;

    const float* Qr = g_q + ((b * H_ + h) * S_ + row) * HD_;
    const float* Kb = g_k + ((size_t)(b * H_ + h) * S_) * HD_;
    const float* Vb = g_v + ((size_t)(b * H_ + h) * S_) * HD_;

    // scale 1/sqrt(64) folded with log2(e): p = exp2(q'.k - m) == exp(score - m_nat)
    const float c = 0.125f * 1.4426950408889634f;

    float q[64];
#pragma unroll
    for (int k = 0; k < 16; ++k) {
        float4 t = *(const float4*)(Qr + k * 4);
        q[k * 4 + 0] = t.x * c; q[k * 4 + 1] = t.y * c;
        q[k * 4 + 2] = t.z * c; q[k * 4 + 3] = t.w * c;
    }

    float acc[64];
#pragma unroll
    for (int k = 0; k < 64; ++k) acc[k] = 0.f;
    float mx = -3.4e38f;
    float l  = 0.f;

    __shared__ __align__(16) float Ks[64][64];
    __shared__ __align__(16) float Vs[64][64];

    for (int j0 = 0; j0 < S_; j0 += 64) {
        __syncthreads();   // previous tile fully consumed
        {
            const float4* ksrc = (const float4*)(Kb + j0 * HD_);
            const float4* vsrc = (const float4*)(Vb + j0 * HD_);
            float4* kdst = (float4*)&Ks[0][0];
            float4* vdst = (float4*)&Vs[0][0];
#pragma unroll
            for (int i = 0; i < 8; ++i) {
                kdst[tid + i * 128] = ksrc[tid + i * 128];
                vdst[tid + i * 128] = vsrc[tid + i * 128];
            }
        }
        __syncthreads();

        for (int j = 0; j < 64; ++j) {
            // dot(q, K_j): 4 partial sums to break the FFMA RAW chain
            float s0 = 0.f, s1 = 0.f, s2 = 0.f, s3 = 0.f;
#pragma unroll
            for (int k = 0; k < 64; k += 4) {
                s0 = fmaf(q[k + 0], Ks[j][k + 0], s0);
                s1 = fmaf(q[k + 1], Ks[j][k + 1], s1);
                s2 = fmaf(q[k + 2], Ks[j][k + 2], s2);
                s3 = fmaf(q[k + 3], Ks[j][k + 3], s3);
            }
            float s = (s0 + s1) + (s2 + s3);

            float p;
            if (s > mx) {
                float corr = exp2f(mx - s);   // exp2(-inf)=0 handles first key
                mx = s;
                l *= corr;
#pragma unroll
                for (int k = 0; k < 64; ++k) acc[k] *= corr;
                p = 1.f;
            } else {
                p = exp2f(s - mx);
            }
            l += p;
#pragma unroll
            for (int k = 0; k < 64; ++k)
                acc[k] = fmaf(p, Vs[j][k], acc[k]);
        }
    }

    const float inv = 1.f / l;
    float* dst = g_ctx + (size_t)(b * S_ + row) * D_ + h * HD_;
#pragma unroll
    for (int k = 0; k < 16; ++k) {
        float4 t = {acc[k * 4 + 0] * inv, acc[k * 4 + 1] * inv,
                    acc[k * 4 + 2] * inv, acc[k * 4 + 3] * inv};
        *(float4*)(dst + k * 4) = t;
    }
}

// ---------------------------------------------------------------------------
// Kernel 3: Output projection. out[m][n] = sum_k ctx[m][k]*W[n][k] + bias[n]
// Same SGEMM structure as kernel 1.
// ---------------------------------------------------------------------------
__global__ __launch_bounds__(256, 2)
void proj_gemm_kernel(const float* __restrict__ W,
                      const float* __restrict__ bias,
                      float* __restrict__ out) {
    __shared__ __align__(16) float As[8][128];
    __shared__ __align__(16) float Bs[8][128];

    const int tid = threadIdx.x;
    const int tx  = tid & 15;
    const int ty  = tid >> 4;
    const int M0  = blockIdx.y * 128;
    const int N0  = blockIdx.x * 128;

    const int lrow = tid >> 1;
    const int lcol = (tid & 1) * 4;
    const float* Aptr = g_ctx + (M0 + lrow) * D_ + lcol;
    const float* Bptr = W + (N0 + lrow) * D_ + lcol;

    float acc[8][8];
#pragma unroll
    for (int i = 0; i < 8; ++i)
#pragma unroll
        for (int j = 0; j < 8; ++j) acc[i][j] = 0.f;

    for (int k0 = 0; k0 < D_; k0 += 8) {
        float4 a = *(const float4*)(Aptr + k0);
        float4 b = *(const float4*)(Bptr + k0);
        As[lcol + 0][lrow] = a.x; As[lcol + 1][lrow] = a.y;
        As[lcol + 2][lrow] = a.z; As[lcol + 3][lrow] = a.w;
        Bs[lcol + 0][lrow] = b.x; Bs[lcol + 1][lrow] = b.y;
        Bs[lcol + 2][lrow] = b.z; Bs[lcol + 3][lrow] = b.w;
        __syncthreads();

#pragma unroll
        for (int k = 0; k < 8; ++k) {
            float4 a0 = *(const float4*)&As[k][ty * 8];
            float4 a1 = *(const float4*)&As[k][ty * 8 + 4];
            float4 b0 = *(const float4*)&Bs[k][tx * 8];
            float4 b1 = *(const float4*)&Bs[k][tx * 8 + 4];
            float ar[8] = {a0.x, a0.y, a0.z, a0.w, a1.x, a1.y, a1.z, a1.w};
            float br[8] = {b0.x, b0.y, b0.z, b0.w, b1.x, b1.y, b1.z, b1.w};
#pragma unroll
            for (int i = 0; i < 8; ++i)
#pragma unroll
                for (int j = 0; j < 8; ++j)
                    acc[i][j] = fmaf(ar[i], br[j], acc[i][j]);
        }
        __syncthreads();
    }

    const int n0 = N0 + tx * 8;
    float bv[8];
#pragma unroll
    for (int j = 0; j < 8; ++j) bv[j] = bias[n0 + j];

#pragma unroll
    for (int i = 0; i < 8; ++i) {
        const int m = M0 + ty * 8 + i;
        float* dst = out + (size_t)m * D_ + n0;
        float4 v0 = {acc[i][0] + bv[0], acc[i][1] + bv[1],
                     acc[i][2] + bv[2], acc[i][3] + bv[3]};
        float4 v1 = {acc[i][4] + bv[4], acc[i][5] + bv[5],
                     acc[i][6] + bv[6], acc[i][7] + bv[7]};
        *(float4*)(dst)     = v0;
        *(float4*)(dst + 4) = v1;
    }
}

// ---------------------------------------------------------------------------
extern "C" void kernel_launch(void* const* d_in, const int* in_sizes, int n_in,
                              void* d_out, int out_size) {
    const float* x      = (const float*)d_in[0];
    const float* qkv_w  = (const float*)d_in[1];
    const float* qkv_b  = (const float*)d_in[2];
    const float* proj_w = (const float*)d_in[3];
    const float* proj_b = (const float*)d_in[4];
    float* out          = (float*)d_out;

    dim3 g1(N3 / 128, MTOT / 128);     // (24, 64)
    qkv_gemm_kernel<<<g1, 256>>>(x, qkv_w, qkv_b);

    dim3 g2(S_ / 128, H_, B_);         // (16, 16, 4)
    flash_attn_kernel<<<g2, 128>>>();

    dim3 g3(D_ / 128, MTOT / 128);     // (8, 64)
    proj_gemm_kernel<<<g3, 256>>>(proj_w, proj_b, out);
}

// round 5
// speedup vs baseline: 1.2032x; 1.2032x over previous
#include <cuda_runtime.h>
#include <cuda_bf16.h>
#include <cstdint>

// Problem shape
#define B_   4
#define H_   16
#define S_   2048
#define HD_  64
#define D_   1024
#define MTOT (B_ * S_)   // 8192
#define N3   (3 * D_)    // 3072
#define K3   3072        // split-K': [hi | mid | lo-combo]

// ---------------------------------------------------------------------------
// Device scratch (static — no runtime allocation)
// ---------------------------------------------------------------------------
__device__ float g_q[B_ * H_ * S_ * HD_];
__device__ float g_k[B_ * H_ * S_ * HD_];
__device__ float g_v[B_ * H_ * S_ * HD_];
__device__ __nv_bfloat16 g_Xs[MTOT * K3];   // [Xh | Xh | Xl]
__device__ __nv_bfloat16 g_Wq3[N3 * K3];    // [Wh | Wl | Wh]
__device__ __nv_bfloat16 g_Wp3[D_ * K3];    // [Wh | Wl | Wh]
__device__ __nv_bfloat16 g_Cs[MTOT * K3];   // ctx split [Ch | Ch | Cl]

// ---------------------------------------------------------------------------
// Split fp32 [rows x 1024] -> bf16 [rows x 3072].
// mode 0 (A-side): hi -> +0 and +1024, lo -> +2048
// mode 1 (B-side): hi -> +0 and +2048, lo -> +1024
// ---------------------------------------------------------------------------
__global__ void split_kernel(const float* __restrict__ in,
                             __nv_bfloat16* __restrict__ out,
                             int n4, int mode) {
    const int KQ = D_ / 4;   // 256 float4 per row
    for (int i = blockIdx.x * blockDim.x + threadIdx.x; i < n4;
         i += gridDim.x * blockDim.x) {
        int row = i / KQ;
        int kk  = (i - row * KQ) * 4;
        float4 x = ((const float4*)in)[i];
        __nv_bfloat16 h[4], l[4];
        float xs[4] = {x.x, x.y, x.z, x.w};
#pragma unroll
        for (int j = 0; j < 4; ++j) {
            h[j] = __float2bfloat16(xs[j]);
            l[j] = __float2bfloat16(xs[j] - __bfloat162float(h[j]));
        }
        __nv_bfloat16* o = out + (size_t)row * K3 + kk;
        __nv_bfloat162 hp0(h[0], h[1]), hp1(h[2], h[3]);
        __nv_bfloat162 lp0(l[0], l[1]), lp1(l[2], l[3]);
        *(__nv_bfloat162*)(o + 0) = hp0;
        *(__nv_bfloat162*)(o + 2) = hp1;
        if (mode == 0) {
            *(__nv_bfloat162*)(o + D_ + 0)     = hp0;
            *(__nv_bfloat162*)(o + D_ + 2)     = hp1;
            *(__nv_bfloat162*)(o + 2 * D_ + 0) = lp0;
            *(__nv_bfloat162*)(o + 2 * D_ + 2) = lp1;
        } else {
            *(__nv_bfloat162*)(o + D_ + 0)     = lp0;
            *(__nv_bfloat162*)(o + D_ + 2)     = lp1;
            *(__nv_bfloat162*)(o + 2 * D_ + 0) = hp0;
            *(__nv_bfloat162*)(o + 2 * D_ + 2) = hp1;
        }
    }
}

// ---------------------------------------------------------------------------
// HMMA bf16 GEMM core: C[128,128] += A[128,K3] * B[128,K3]^T  (both K-major)
// 256 threads, 8 warps (4M x 2N), warp tile 32x64, mma.m16n8k16.
// Double-buffered cp.async, K-chunk 32, padded smem rows (40 bf16).
// ---------------------------------------------------------------------------
#define KC      32
#define NCHUNK  (K3 / KC)      // 96
#define SROW    40             // padded row (elements)

__device__ __forceinline__ uint32_t smem_u32(const void* p) {
    uint32_t a;
    asm("{ .reg .u64 t; cvta.to.shared.u64 t, %1; cvt.u32.u64 %0, t; }"
        : "=r"(a) : "l"(p));
    return a;
}

__device__ __forceinline__ void ldmat4(uint32_t& r0, uint32_t& r1,
                                       uint32_t& r2, uint32_t& r3,
                                       uint32_t addr) {
    asm volatile("ldmatrix.sync.aligned.m8n8.x4.shared.b16 {%0,%1,%2,%3}, [%4];"
                 : "=r"(r0), "=r"(r1), "=r"(r2), "=r"(r3) : "r"(addr));
}

__device__ __forceinline__ void mma16816(float* c, const uint32_t* a,
                                         const uint32_t* b) {
    asm volatile(
        "mma.sync.aligned.m16n8k16.row.col.f32.bf16.bf16.f32 "
        "{%0,%1,%2,%3}, {%4,%5,%6,%7}, {%8,%9}, {%0,%1,%2,%3};"
        : "+f"(c[0]), "+f"(c[1]), "+f"(c[2]), "+f"(c[3])
        : "r"(a[0]), "r"(a[1]), "r"(a[2]), "r"(a[3]), "r"(b[0]), "r"(b[1]));
}

__device__ __forceinline__ void cp16(uint32_t saddr, const void* gaddr) {
    asm volatile("cp.async.cg.shared.global [%0], [%1], 16;"
                 :: "r"(saddr), "l"(gaddr));
}

// computes acc[2][8][4] for this thread; A at row M0, B at row N0
__device__ __forceinline__ void gemm_core(
    const __nv_bfloat16* __restrict__ A, const __nv_bfloat16* __restrict__ B,
    int M0, int N0, float (*acc)[8][4],
    __nv_bfloat16 (*As)[128 * SROW], __nv_bfloat16 (*Bs)[128 * SROW])
{
    const int tid  = threadIdx.x;
    const int wid  = tid >> 5;
    const int lane = tid & 31;
    const int wm   = (wid & 3) * 32;
    const int wn   = (wid >> 2) * 64;

    const uint32_t sA0 = smem_u32(As[0]);
    const uint32_t sA1 = smem_u32(As[1]);
    const uint32_t sB0 = smem_u32(Bs[0]);
    const uint32_t sB1 = smem_u32(Bs[1]);

    // load-thread mapping: 512 16B-chunks per tile, 2 per thread
    const int c0   = tid;            // chunk ids tid, tid+256
    const int row0 = c0 >> 2,        kc0 = (c0 & 3) * 8;
    const int c1   = tid + 256;
    const int row1 = c1 >> 2,        kc1 = (c1 & 3) * 8;

    // ldmatrix lane addressing
    const int lg = lane >> 3, lr = lane & 7;
    // A: row = base + (g&1)*8 + r ; col = ks + (g>>1)*8
    const int a_row = (lg & 1) * 8 + lr;
    const int a_col = (lg >> 1) * 8;
    // B: row = base + (g>>1)*8 + r ; col = ks + (g&1)*8
    const int b_row = (lg >> 1) * 8 + lr;
    const int b_col = (lg & 1) * 8;

    auto issue = [&](int kc, int buf) {
        const int kb = kc * KC;
        uint32_t sa = buf ? sA1 : sA0;
        uint32_t sb = buf ? sB1 : sB0;
        cp16(sa + (row0 * SROW + kc0) * 2, A + (size_t)(M0 + row0) * K3 + kb + kc0);
        cp16(sa + (row1 * SROW + kc1) * 2, A + (size_t)(M0 + row1) * K3 + kb + kc1);
        cp16(sb + (row0 * SROW + kc0) * 2, B + (size_t)(N0 + row0) * K3 + kb + kc0);
        cp16(sb + (row1 * SROW + kc1) * 2, B + (size_t)(N0 + row1) * K3 + kb + kc1);
        asm volatile("cp.async.commit_group;" ::: "memory");
    };

    issue(0, 0);

    for (int kc = 0; kc < NCHUNK; ++kc) {
        if (kc + 1 < NCHUNK) {
            issue(kc + 1, (kc + 1) & 1);
            asm volatile("cp.async.wait_group 1;" ::: "memory");
        } else {
            asm volatile("cp.async.wait_group 0;" ::: "memory");
        }
        __syncthreads();

        const uint32_t sa = (kc & 1) ? sA1 : sA0;
        const uint32_t sb = (kc & 1) ? sB1 : sB0;

#pragma unroll
        for (int ks = 0; ks < KC; ks += 16) {
            uint32_t a[2][4], b[8][2];
#pragma unroll
            for (int mt = 0; mt < 2; ++mt) {
                uint32_t addr = sa + (((wm + mt * 16 + a_row) * SROW) +
                                      ks + a_col) * 2;
                ldmat4(a[mt][0], a[mt][1], a[mt][2], a[mt][3], addr);
            }
#pragma unroll
            for (int np = 0; np < 4; ++np) {
                uint32_t addr = sb + (((wn + np * 16 + b_row) * SROW) +
                                      ks + b_col) * 2;
                ldmat4(b[2 * np][0], b[2 * np][1],
                       b[2 * np + 1][0], b[2 * np + 1][1], addr);
            }
#pragma unroll
            for (int mt = 0; mt < 2; ++mt)
#pragma unroll
                for (int nt = 0; nt < 8; ++nt)
                    mma16816(acc[mt][nt], a[mt], b[nt]);
        }
        __syncthreads();
    }
}

// ---------------------------------------------------------------------------
// Kernel 1: QKV projection -> scatter to g_q/g_k/g_v [B][H][S][64]
// ---------------------------------------------------------------------------
__global__ __launch_bounds__(256)
void qkv_mma_kernel(const float* __restrict__ bias) {
    __shared__ __align__(16) __nv_bfloat16 As[2][128 * SROW];
    __shared__ __align__(16) __nv_bfloat16 Bs[2][128 * SROW];

    const int M0 = blockIdx.y * 128;
    const int N0 = blockIdx.x * 128;

    float acc[2][8][4];
#pragma unroll
    for (int i = 0; i < 2; ++i)
#pragma unroll
        for (int j = 0; j < 8; ++j)
#pragma unroll
            for (int k = 0; k < 4; ++k) acc[i][j][k] = 0.f;

    gemm_core(g_Xs, g_Wq3, M0, N0, acc, As, Bs);

    const int wid  = threadIdx.x >> 5;
    const int lane = threadIdx.x & 31;
    const int wm   = (wid & 3) * 32;
    const int wn   = (wid >> 2) * 64;

#pragma unroll
    for (int mt = 0; mt < 2; ++mt) {
#pragma unroll
        for (int nt = 0; nt < 8; ++nt) {
            const int col = N0 + wn + nt * 8 + (lane & 3) * 2;
            const int t   = col >> 10;
            const int d   = col & 1023;
            const int h   = d >> 6;
            const int dd  = d & 63;
            float* tbase = (t == 0) ? g_q : (t == 1) ? g_k : g_v;
            const float bv0 = bias[col];
            const float bv1 = bias[col + 1];
#pragma unroll
            for (int half = 0; half < 2; ++half) {
                const int m  = M0 + wm + mt * 16 + (lane >> 2) + half * 8;
                const int bb = m >> 11;
                const int s  = m & 2047;
                float* dst = tbase +
                    ((((size_t)bb * H_ + h) * S_ + s) * HD_ + dd);
                float2 v = {acc[mt][nt][half * 2 + 0] + bv0,
                            acc[mt][nt][half * 2 + 1] + bv1};
                *(float2*)dst = v;
            }
        }
    }
}

// ---------------------------------------------------------------------------
// Kernel 3: Output projection -> fp32 out
// ---------------------------------------------------------------------------
__global__ __launch_bounds__(256)
void proj_mma_kernel(const float* __restrict__ bias, float* __restrict__ out) {
    __shared__ __align__(16) __nv_bfloat16 As[2][128 * SROW];
    __shared__ __align__(16) __nv_bfloat16 Bs[2][128 * SROW];

    const int M0 = blockIdx.y * 128;
    const int N0 = blockIdx.x * 128;

    float acc[2][8][4];
#pragma unroll
    for (int i = 0; i < 2; ++i)
#pragma unroll
        for (int j = 0; j < 8; ++j)
#pragma unroll
            for (int k = 0; k < 4; ++k) acc[i][j][k] = 0.f;

    gemm_core(g_Cs, g_Wp3, M0, N0, acc, As, Bs);

    const int wid  = threadIdx.x >> 5;
    const int lane = threadIdx.x & 31;
    const int wm   = (wid & 3) * 32;
    const int wn   = (wid >> 2) * 64;

#pragma unroll
    for (int mt = 0; mt < 2; ++mt) {
#pragma unroll
        for (int nt = 0; nt < 8; ++nt) {
            const int col = N0 + wn + nt * 8 + (lane & 3) * 2;
            const float bv0 = bias[col];
            const float bv1 = bias[col + 1];
#pragma unroll
            for (int half = 0; half < 2; ++half) {
                const int m = M0 + wm + mt * 16 + (lane >> 2) + half * 8;
                float2 v = {acc[mt][nt][half * 2 + 0] + bv0,
                            acc[mt][nt][half * 2 + 1] + bv1};
                *(float2*)(out + (size_t)m * D_ + col) = v;
            }
        }
    }
}

// ---------------------------------------------------------------------------
// Kernel 2: Flash attention (fp32). 256 threads, 1 query row per thread.
// Writes ctx split [Ch | Ch | Cl] into g_Cs (row stride K3).
// ---------------------------------------------------------------------------
__global__ __launch_bounds__(256)
void flash_attn_kernel() {
    const int b   = blockIdx.z;
    const int h   = blockIdx.y;
    const int tid = threadIdx.x;
    const int row = blockIdx.x * 256 + tid;

    const float* Qr = g_q + (((size_t)b * H_ + h) * S_ + row) * HD_;
    const float* Kb = g_k + ((size_t)(b * H_ + h) * S_) * HD_;
    const float* Vb = g_v + ((size_t)(b * H_ + h) * S_) * HD_;

    const float c = 0.125f;   // 1/sqrt(64)

    float q[64];
#pragma unroll
    for (int k = 0; k < 16; ++k) {
        float4 t = *(const float4*)(Qr + k * 4);
        q[k * 4 + 0] = t.x * c; q[k * 4 + 1] = t.y * c;
        q[k * 4 + 2] = t.z * c; q[k * 4 + 3] = t.w * c;
    }

    float acc[64];
#pragma unroll
    for (int k = 0; k < 64; ++k) acc[k] = 0.f;
    float mx = -3.4e38f;
    float l  = 0.f;

    __shared__ __align__(16) float Ks[64][64];
    __shared__ __align__(16) float Vs[64][64];

    for (int j0 = 0; j0 < S_; j0 += 64) {
        __syncthreads();
        {
            const float4* ksrc = (const float4*)(Kb + j0 * HD_);
            const float4* vsrc = (const float4*)(Vb + j0 * HD_);
            float4* kdst = (float4*)&Ks[0][0];
            float4* vdst = (float4*)&Vs[0][0];
#pragma unroll
            for (int i = 0; i < 4; ++i) {
                kdst[tid + i * 256] = ksrc[tid + i * 256];
                vdst[tid + i * 256] = vsrc[tid + i * 256];
            }
        }
        __syncthreads();

        for (int j = 0; j < 64; ++j) {
            float s0 = 0.f, s1 = 0.f, s2 = 0.f, s3 = 0.f;
#pragma unroll
            for (int k = 0; k < 64; k += 4) {
                s0 = fmaf(q[k + 0], Ks[j][k + 0], s0);
                s1 = fmaf(q[k + 1], Ks[j][k + 1], s1);
                s2 = fmaf(q[k + 2], Ks[j][k + 2], s2);
                s3 = fmaf(q[k + 3], Ks[j][k + 3], s3);
            }
            float s = (s0 + s1) + (s2 + s3);

            float p;
            if (s > mx) {
                float corr = __expf(mx - s);
                mx = s;
                l *= corr;
#pragma unroll
                for (int k = 0; k < 64; ++k) acc[k] *= corr;
                p = 1.f;
            } else {
                p = __expf(s - mx);
            }
            l += p;
#pragma unroll
            for (int k = 0; k < 64; ++k)
                acc[k] = fmaf(p, Vs[j][k], acc[k]);
        }
    }

    const float inv = 1.f / l;
    __nv_bfloat16* obase = g_Cs + (size_t)(b * S_ + row) * K3 + h * HD_;
#pragma unroll
    for (int k = 0; k < 64; k += 2) {
        float o0 = acc[k + 0] * inv;
        float o1 = acc[k + 1] * inv;
        __nv_bfloat16 h0 = __float2bfloat16(o0);
        __nv_bfloat16 h1 = __float2bfloat16(o1);
        __nv_bfloat16 l0 = __float2bfloat16(o0 - __bfloat162float(h0));
        __nv_bfloat16 l1 = __float2bfloat16(o1 - __bfloat162float(h1));
        __nv_bfloat162 hp(h0, h1), lp(l0, l1);
        *(__nv_bfloat162*)(obase + k)            = hp;   // hi
        *(__nv_bfloat162*)(obase + D_ + k)       = hp;   // hi (2nd copy)
        *(__nv_bfloat162*)(obase + 2 * D_ + k)   = lp;   // lo
    }
}

// ---------------------------------------------------------------------------
extern "C" void kernel_launch(void* const* d_in, const int* in_sizes, int n_in,
                              void* d_out, int out_size) {
    const float* x      = (const float*)d_in[0];
    const float* qkv_w  = (const float*)d_in[1];
    const float* qkv_b  = (const float*)d_in[2];
    const float* proj_w = (const float*)d_in[3];
    const float* proj_b = (const float*)d_in[4];
    float* out          = (float*)d_out;

    __nv_bfloat16 *xs, *wq3, *wp3;
    cudaGetSymbolAddress((void**)&xs,  g_Xs);
    cudaGetSymbolAddress((void**)&wq3, g_Wq3);
    cudaGetSymbolAddress((void**)&wp3, g_Wp3);

    split_kernel<<<1024, 256>>>(x,      xs,  MTOT * D_ / 4, 0);  // A-side
    split_kernel<<<512,  256>>>(qkv_w,  wq3, N3 * D_ / 4,  1);   // B-side
    split_kernel<<<256,  256>>>(proj_w, wp3, D_ * D_ / 4,  1);   // B-side

    dim3 g1(N3 / 128, MTOT / 128);     // (24, 64)
    qkv_mma_kernel<<<g1, 256>>>(qkv_b);

    dim3 g2(S_ / 256, H_, B_);         // (8, 16, 4)
    flash_attn_kernel<<<g2, 256>>>();

    dim3 g3(D_ / 128, MTOT / 128);     // (8, 64)
    proj_mma_kernel<<<g3, 256>>>(proj_b, out);
}

// round 7
// speedup vs baseline: 3.1181x; 2.5915x over previous
#include <cuda_runtime.h>
#include <cuda_bf16.h>
#include <cstdint>

// Problem shape
#define B_   4
#define H_   16
#define S_   2048
#define HD_  64
#define D_   1024
#define MTOT (B_ * S_)   // 8192
#define N3   (3 * D_)    // 3072
#define K3   3072        // split-K': [hi | mid | lo-combo]

// ---------------------------------------------------------------------------
// Device scratch (static — no runtime allocation)
// ---------------------------------------------------------------------------
__device__ __nv_bfloat16 g_qh[B_ * H_ * S_ * HD_];
__device__ __nv_bfloat16 g_ql[B_ * H_ * S_ * HD_];
__device__ __nv_bfloat16 g_kh[B_ * H_ * S_ * HD_];
__device__ __nv_bfloat16 g_kl[B_ * H_ * S_ * HD_];
__device__ __nv_bfloat16 g_vh[B_ * H_ * S_ * HD_];
__device__ __nv_bfloat16 g_vl[B_ * H_ * S_ * HD_];
__device__ __nv_bfloat16 g_Xs[MTOT * K3];   // [Xh | Xh | Xl]
__device__ __nv_bfloat16 g_Wq3[N3 * K3];    // [Wh | Wl | Wh]
__device__ __nv_bfloat16 g_Wp3[D_ * K3];    // [Wh | Wl | Wh]
__device__ __nv_bfloat16 g_Cs[MTOT * K3];   // ctx split [Ch | Ch | Cl]

// ---------------------------------------------------------------------------
// small helpers
// ---------------------------------------------------------------------------
__device__ __forceinline__ uint32_t smem_u32(const void* p) {
    uint32_t a;
    asm("{ .reg .u64 t; cvta.to.shared.u64 t, %1; cvt.u32.u64 %0, t; }"
        : "=r"(a) : "l"(p));
    return a;
}
__device__ __forceinline__ void ldmat4(uint32_t& r0, uint32_t& r1,
                                       uint32_t& r2, uint32_t& r3,
                                       uint32_t addr) {
    asm volatile("ldmatrix.sync.aligned.m8n8.x4.shared.b16 {%0,%1,%2,%3}, [%4];"
                 : "=r"(r0), "=r"(r1), "=r"(r2), "=r"(r3) : "r"(addr));
}
__device__ __forceinline__ void ldmat4t(uint32_t& r0, uint32_t& r1,
                                        uint32_t& r2, uint32_t& r3,
                                        uint32_t addr) {
    asm volatile("ldmatrix.sync.aligned.m8n8.x4.trans.shared.b16 {%0,%1,%2,%3}, [%4];"
                 : "=r"(r0), "=r"(r1), "=r"(r2), "=r"(r3) : "r"(addr));
}
__device__ __forceinline__ void mma16816(float* c, const uint32_t* a,
                                         const uint32_t* b) {
    asm volatile(
        "mma.sync.aligned.m16n8k16.row.col.f32.bf16.bf16.f32 "
        "{%0,%1,%2,%3}, {%4,%5,%6,%7}, {%8,%9}, {%0,%1,%2,%3};"
        : "+f"(c[0]), "+f"(c[1]), "+f"(c[2]), "+f"(c[3])
        : "r"(a[0]), "r"(a[1]), "r"(a[2]), "r"(a[3]), "r"(b[0]), "r"(b[1]));
}
__device__ __forceinline__ void cp16(uint32_t saddr, const void* gaddr) {
    asm volatile("cp.async.cg.shared.global [%0], [%1], 16;"
                 :: "r"(saddr), "l"(gaddr));
}
__device__ __forceinline__ float ex2(float x) {
    float y;
    asm("ex2.approx.ftz.f32 %0, %1;" : "=f"(y) : "f"(x));
    return y;
}
// pack (e0 -> low half, e1 -> high half)
__device__ __forceinline__ uint32_t packbf(float e0, float e1) {
    uint32_t r;
    asm("cvt.rn.satfinite.bf16x2.f32 %0, %1, %2;" : "=r"(r) : "f"(e1), "f"(e0));
    return r;
}
__device__ __forceinline__ void split2(float v0, float v1,
                                       __nv_bfloat162& hp, __nv_bfloat162& lp) {
    __nv_bfloat16 h0 = __float2bfloat16(v0);
    __nv_bfloat16 h1 = __float2bfloat16(v1);
    hp = __nv_bfloat162(h0, h1);
    lp = __nv_bfloat162(__float2bfloat16(v0 - __bfloat162float(h0)),
                        __float2bfloat16(v1 - __bfloat162float(h1)));
}

// ---------------------------------------------------------------------------
// Split fp32 [rows x 1024] -> bf16 [rows x 3072].
// mode 0 (A-side): [hi | hi | lo] ; mode 1 (B-side): [hi | lo | hi]
// ---------------------------------------------------------------------------
__global__ void split_kernel(const float* __restrict__ in,
                             __nv_bfloat16* __restrict__ out,
                             int n4, int mode) {
    const int KQ = D_ / 4;
    for (int i = blockIdx.x * blockDim.x + threadIdx.x; i < n4;
         i += gridDim.x * blockDim.x) {
        int row = i / KQ;
        int kk  = (i - row * KQ) * 4;
        float4 x = ((const float4*)in)[i];
        __nv_bfloat162 hp0, hp1, lp0, lp1;
        split2(x.x, x.y, hp0, lp0);
        split2(x.z, x.w, hp1, lp1);
        __nv_bfloat16* o = out + (size_t)row * K3 + kk;
        *(__nv_bfloat162*)(o + 0) = hp0;
        *(__nv_bfloat162*)(o + 2) = hp1;
        if (mode == 0) {
            *(__nv_bfloat162*)(o + D_ + 0)     = hp0;
            *(__nv_bfloat162*)(o + D_ + 2)     = hp1;
            *(__nv_bfloat162*)(o + 2 * D_ + 0) = lp0;
            *(__nv_bfloat162*)(o + 2 * D_ + 2) = lp1;
        } else {
            *(__nv_bfloat162*)(o + D_ + 0)     = lp0;
            *(__nv_bfloat162*)(o + D_ + 2)     = lp1;
            *(__nv_bfloat162*)(o + 2 * D_ + 0) = hp0;
            *(__nv_bfloat162*)(o + 2 * D_ + 2) = hp1;
        }
    }
}

// ---------------------------------------------------------------------------
// HMMA bf16 GEMM core: C[128,128] += A[128,K3] * B[128,K3]^T (both K-major)
// 256 threads, 8 warps (4M x 2N), warp tile 32x64. 3-stage cp.async pipeline.
// ---------------------------------------------------------------------------
#define KC      32
#define NCHUNK  (K3 / KC)      // 96
#define SROW    40             // padded row (elements)
#define STAGE_BYTES 20480      // A(10240) + B(10240)
#define GEMM_SMEM (3 * STAGE_BYTES)

__device__ __forceinline__ void gemm_core(
    const __nv_bfloat16* __restrict__ A, const __nv_bfloat16* __restrict__ B,
    int M0, int N0, float (*acc)[8][4], char* smem)
{
    const int tid  = threadIdx.x;
    const int wid  = tid >> 5;
    const int lane = tid & 31;
    const int wm   = (wid & 3) * 32;
    const int wn   = (wid >> 2) * 64;
    const uint32_t s0 = smem_u32(smem);

    const int c0 = tid,       row0 = c0 >> 2, kc0 = (c0 & 3) * 8;
    const int c1 = tid + 256, row1 = c1 >> 2, kc1 = (c1 & 3) * 8;

    const int lg = lane >> 3, lr = lane & 7;
    const int a_row = (lg & 1) * 8 + lr;
    const int a_col = (lg >> 1) * 8;
    const int b_row = (lg >> 1) * 8 + lr;
    const int b_col = (lg & 1) * 8;

    auto issue = [&](int kc, int stg) {
        const int kb = kc * KC;
        uint32_t sa = s0 + stg * STAGE_BYTES;
        uint32_t sb = sa + 10240;
        cp16(sa + (row0 * SROW + kc0) * 2, A + (size_t)(M0 + row0) * K3 + kb + kc0);
        cp16(sa + (row1 * SROW + kc1) * 2, A + (size_t)(M0 + row1) * K3 + kb + kc1);
        cp16(sb + (row0 * SROW + kc0) * 2, B + (size_t)(N0 + row0) * K3 + kb + kc0);
        cp16(sb + (row1 * SROW + kc1) * 2, B + (size_t)(N0 + row1) * K3 + kb + kc1);
        asm volatile("cp.async.commit_group;" ::: "memory");
    };

    issue(0, 0);
    issue(1, 1);

    for (int kc = 0; kc < NCHUNK; ++kc) {
        if (kc + 2 < NCHUNK) issue(kc + 2, (kc + 2) % 3);
        if (kc < NCHUNK - 2)
            asm volatile("cp.async.wait_group 2;" ::: "memory");
        else if (kc == NCHUNK - 2)
            asm volatile("cp.async.wait_group 1;" ::: "memory");
        else
            asm volatile("cp.async.wait_group 0;" ::: "memory");
        __syncthreads();

        const uint32_t sa = s0 + (kc % 3) * STAGE_BYTES;
        const uint32_t sb = sa + 10240;

#pragma unroll
        for (int ks = 0; ks < KC; ks += 16) {
            uint32_t a[2][4], b[8][2];
#pragma unroll
            for (int mt = 0; mt < 2; ++mt) {
                uint32_t addr = sa + (((wm + mt * 16 + a_row) * SROW) +
                                      ks + a_col) * 2;
                ldmat4(a[mt][0], a[mt][1], a[mt][2], a[mt][3], addr);
            }
#pragma unroll
            for (int np = 0; np < 4; ++np) {
                uint32_t addr = sb + (((wn + np * 16 + b_row) * SROW) +
                                      ks + b_col) * 2;
                ldmat4(b[2 * np][0], b[2 * np][1],
                       b[2 * np + 1][0], b[2 * np + 1][1], addr);
            }
#pragma unroll
            for (int mt = 0; mt < 2; ++mt)
#pragma unroll
                for (int nt = 0; nt < 8; ++nt)
                    mma16816(acc[mt][nt], a[mt], b[nt]);
        }
        __syncthreads();
    }
}

// ---------------------------------------------------------------------------
// Kernel 1: QKV projection -> split-bf16 q/k/v [B][H][S][64] (q pre-scaled)
// ---------------------------------------------------------------------------
__global__ __launch_bounds__(256)
void qkv_mma_kernel(const float* __restrict__ bias) {
    extern __shared__ char smem[];
    const int M0 = blockIdx.y * 128;
    const int N0 = blockIdx.x * 128;

    float acc[2][8][4];
#pragma unroll
    for (int i = 0; i < 2; ++i)
#pragma unroll
        for (int j = 0; j < 8; ++j)
#pragma unroll
            for (int k = 0; k < 4; ++k) acc[i][j][k] = 0.f;

    gemm_core(g_Xs, g_Wq3, M0, N0, acc, smem);

    const int wid  = threadIdx.x >> 5;
    const int lane = threadIdx.x & 31;
    const int wm   = (wid & 3) * 32;
    const int wn   = (wid >> 2) * 64;
    const float QSC = 0.125f * 1.4426950408889634f;  // scale * log2(e)

#pragma unroll
    for (int mt = 0; mt < 2; ++mt) {
#pragma unroll
        for (int nt = 0; nt < 8; ++nt) {
            const int col = N0 + wn + nt * 8 + (lane & 3) * 2;
            const int t   = col >> 10;
            const int d   = col & 1023;
            const int hh  = d >> 6;
            const int dd  = d & 63;
            __nv_bfloat16 *dh, *dl;
            if (t == 0)      { dh = g_qh; dl = g_ql; }
            else if (t == 1) { dh = g_kh; dl = g_kl; }
            else             { dh = g_vh; dl = g_vl; }
            const float sc  = (t == 0) ? QSC : 1.f;
            const float bv0 = bias[col];
            const float bv1 = bias[col + 1];
#pragma unroll
            for (int half = 0; half < 2; ++half) {
                const int m  = M0 + wm + mt * 16 + (lane >> 2) + half * 8;
                const int bb = m >> 11;
                const int s  = m & 2047;
                const size_t idx =
                    (((size_t)bb * H_ + hh) * S_ + s) * HD_ + dd;
                float v0 = (acc[mt][nt][half * 2 + 0] + bv0) * sc;
                float v1 = (acc[mt][nt][half * 2 + 1] + bv1) * sc;
                __nv_bfloat162 hp, lp;
                split2(v0, v1, hp, lp);
                *(__nv_bfloat162*)(dh + idx) = hp;
                *(__nv_bfloat162*)(dl + idx) = lp;
            }
        }
    }
}

// ---------------------------------------------------------------------------
// Kernel 3: Output projection -> fp32 out
// ---------------------------------------------------------------------------
__global__ __launch_bounds__(256)
void proj_mma_kernel(const float* __restrict__ bias, float* __restrict__ out) {
    extern __shared__ char smem[];
    const int M0 = blockIdx.y * 128;
    const int N0 = blockIdx.x * 128;

    float acc[2][8][4];
#pragma unroll
    for (int i = 0; i < 2; ++i)
#pragma unroll
        for (int j = 0; j < 8; ++j)
#pragma unroll
            for (int k = 0; k < 4; ++k) acc[i][j][k] = 0.f;

    gemm_core(g_Cs, g_Wp3, M0, N0, acc, smem);

    const int wid  = threadIdx.x >> 5;
    const int lane = threadIdx.x & 31;
    const int wm   = (wid & 3) * 32;
    const int wn   = (wid >> 2) * 64;

#pragma unroll
    for (int mt = 0; mt < 2; ++mt) {
#pragma unroll
        for (int nt = 0; nt < 8; ++nt) {
            const int col = N0 + wn + nt * 8 + (lane & 3) * 2;
            const float bv0 = bias[col];
            const float bv1 = bias[col + 1];
#pragma unroll
            for (int half = 0; half < 2; ++half) {
                const int m = M0 + wm + mt * 16 + (lane >> 2) + half * 8;
                float2 v = {acc[mt][nt][half * 2 + 0] + bv0,
                            acc[mt][nt][half * 2 + 1] + bv1};
                *(float2*)(out + (size_t)m * D_ + col) = v;
            }
        }
    }
}

// ---------------------------------------------------------------------------
// Kernel 2: Flash attention on HMMA with split-bf16 QK^T and PV.
// 256 threads (8 warps); CTA = 128 q-rows of one (b,h). Key tiles of 64.
// Warp owns m16 x 64; P accumulator frags reused as A operands for PV.
// ---------------------------------------------------------------------------
#define SR2 72                       // padded row for 64-elem tiles
#define QSTG  18432                  // 128*72*2 bytes (Q staging, per array)
#define KVBUF 36864                  // per-buffer bytes (4 arrays of 9216)
#define FLASH_SMEM (2 * KVBUF)       // 73728

__global__ __launch_bounds__(256)
void flash_mma_kernel() {
    extern __shared__ char sm[];
    const int b = blockIdx.z, h = blockIdx.y;
    const int qbase = blockIdx.x * 128;
    const int tid = threadIdx.x, wid = tid >> 5, lane = tid & 31;
    const size_t bh = (size_t)b * H_ + h;
    const __nv_bfloat16* Qh = g_qh + bh * S_ * HD_;
    const __nv_bfloat16* Ql = g_ql + bh * S_ * HD_;
    const __nv_bfloat16* Kh = g_kh + bh * S_ * HD_;
    const __nv_bfloat16* Kl = g_kl + bh * S_ * HD_;
    const __nv_bfloat16* Vh = g_vh + bh * S_ * HD_;
    const __nv_bfloat16* Vl = g_vl + bh * S_ * HD_;
    const uint32_t smb = smem_u32(sm);

    // ---- stage Q tiles (reuses buffer space), load A-frags to registers ----
#pragma unroll
    for (int i = 0; i < 4; ++i) {
        int c = tid + i * 256;             // 0..1023
        int row = c >> 3, kc = (c & 7) * 8;
        uint32_t dof = (uint32_t)(row * SR2 + kc) * 2;
        const size_t gi = (size_t)(qbase + row) * HD_ + kc;
        cp16(smb + dof,        Qh + gi);
        cp16(smb + QSTG + dof, Ql + gi);
    }
    asm volatile("cp.async.commit_group;" ::: "memory");
    asm volatile("cp.async.wait_group 0;" ::: "memory");
    __syncthreads();

    const int lg = lane >> 3, lr = lane & 7;
    const int a_row = 16 * wid + (lg & 1) * 8 + lr;
    const int a_col = (lg >> 1) * 8;
    uint32_t qhf[4][4], qlf[4][4];
#pragma unroll
    for (int c = 0; c < 4; ++c) {
        uint32_t ad = smb + (uint32_t)(a_row * SR2 + c * 16 + a_col) * 2;
        ldmat4(qhf[c][0], qhf[c][1], qhf[c][2], qhf[c][3], ad);
        ldmat4(qlf[c][0], qlf[c][1], qlf[c][2], qlf[c][3], ad + QSTG);
    }
    __syncthreads();   // Q staging area is now free for KV buffers

    // KV tile loader: arrays at +0(Kh) +9216(Kl) +18432(Vh) +27648(Vl)
    auto issueKV = [&](int t, int buf) {
        const uint32_t bb = smb + buf * KVBUF;
        const size_t rb = (size_t)t * 64;
#pragma unroll
        for (int i = 0; i < 2; ++i) {
            int c = tid + i * 256;          // 0..511
            int row = c >> 3, kc = (c & 7) * 8;
            uint32_t dq = (uint32_t)(row * SR2 + kc) * 2;
            const size_t gi = (rb + row) * HD_ + kc;
            cp16(bb + dq,         Kh + gi);
            cp16(bb + 9216 + dq,  Kl + gi);
            cp16(bb + 18432 + dq, Vh + gi);
            cp16(bb + 27648 + dq, Vl + gi);
        }
        asm volatile("cp.async.commit_group;" ::: "memory");
    };

    const int b_row = (lg >> 1) * 8 + lr, b_col = (lg & 1) * 8;  // QK (non-trans)
    const int t_row = (lg & 1) * 8 + lr, t_col = (lg >> 1) * 8;  // PV (trans)

    float o[8][4];
#pragma unroll
    for (int j = 0; j < 8; ++j)
#pragma unroll
        for (int e = 0; e < 4; ++e) o[j][e] = 0.f;
    float m0 = -1e30f, m1 = -1e30f, l0 = 0.f, l1 = 0.f;

    issueKV(0, 0);

    for (int t = 0; t < S_ / 64; ++t) {
        if (t + 1 < S_ / 64) {
            issueKV(t + 1, (t + 1) & 1);
            asm volatile("cp.async.wait_group 1;" ::: "memory");
        } else {
            asm volatile("cp.async.wait_group 0;" ::: "memory");
        }
        __syncthreads();
        const uint32_t kb = smb + (t & 1) * KVBUF;

        // ---- QK^T: s[128x64] split across warps (m16 each) ----
        float s[8][4];
#pragma unroll
        for (int j = 0; j < 8; ++j)
#pragma unroll
            for (int e = 0; e < 4; ++e) s[j][e] = 0.f;

        auto qk_pass = [&](uint32_t (*af)[4], uint32_t kbase) {
#pragma unroll
            for (int c = 0; c < 4; ++c) {
                uint32_t bf[8][2];
#pragma unroll
                for (int nb = 0; nb < 4; ++nb) {
                    uint32_t addr = kbase +
                        (uint32_t)((nb * 16 + b_row) * SR2 + c * 16 + b_col) * 2;
                    ldmat4(bf[2 * nb][0], bf[2 * nb][1],
                           bf[2 * nb + 1][0], bf[2 * nb + 1][1], addr);
                }
#pragma unroll
                for (int j = 0; j < 8; ++j) mma16816(s[j], af[c], bf[j]);
            }
        };
        qk_pass(qhf, kb);            // Qh*Kh
        qk_pass(qhf, kb + 9216);     // Qh*Kl
        qk_pass(qlf, kb);            // Ql*Kh

        // ---- online softmax (exp2 domain; scale folded into q) ----
        float mn0 = s[0][0], mn1 = s[0][2];
#pragma unroll
        for (int j = 0; j < 8; ++j) {
            mn0 = fmaxf(mn0, fmaxf(s[j][0], s[j][1]));
            mn1 = fmaxf(mn1, fmaxf(s[j][2], s[j][3]));
        }
        mn0 = fmaxf(mn0, __shfl_xor_sync(0xffffffffu, mn0, 1));
        mn0 = fmaxf(mn0, __shfl_xor_sync(0xffffffffu, mn0, 2));
        mn1 = fmaxf(mn1, __shfl_xor_sync(0xffffffffu, mn1, 1));
        mn1 = fmaxf(mn1, __shfl_xor_sync(0xffffffffu, mn1, 2));
        const float nm0 = fmaxf(m0, mn0), nm1 = fmaxf(m1, mn1);
        const float cr0 = ex2(m0 - nm0), cr1 = ex2(m1 - nm1);
        m0 = nm0; m1 = nm1;
        l0 *= cr0; l1 *= cr1;
#pragma unroll
        for (int j = 0; j < 8; ++j) {
            o[j][0] *= cr0; o[j][1] *= cr0;
            o[j][2] *= cr1; o[j][3] *= cr1;
        }
        float rs0 = 0.f, rs1 = 0.f;
#pragma unroll
        for (int j = 0; j < 8; ++j) {
            s[j][0] = ex2(s[j][0] - m0); s[j][1] = ex2(s[j][1] - m0);
            s[j][2] = ex2(s[j][2] - m1); s[j][3] = ex2(s[j][3] - m1);
            rs0 += s[j][0] + s[j][1];
            rs1 += s[j][2] + s[j][3];
        }
        l0 += rs0; l1 += rs1;   // per-lane partial; quad-reduced at the end

        // ---- P frags (hi/lo) directly from accumulator layout ----
        uint32_t phi[4][4], plo[4][4];
#pragma unroll
        for (int c = 0; c < 4; ++c) {
            phi[c][0] = packbf(s[2 * c][0],     s[2 * c][1]);
            phi[c][1] = packbf(s[2 * c][2],     s[2 * c][3]);
            phi[c][2] = packbf(s[2 * c + 1][0], s[2 * c + 1][1]);
            phi[c][3] = packbf(s[2 * c + 1][2], s[2 * c + 1][3]);
#pragma unroll
            for (int k = 0; k < 4; ++k) {
                const int jj = 2 * c + (k >> 1);
                const int e0 = (k & 1) * 2;
                uint32_t hp = phi[c][k];
                float h0 = __uint_as_float(hp << 16);
                float h1 = __uint_as_float(hp & 0xffff0000u);
                plo[c][k] = packbf(s[jj][e0] - h0, s[jj][e0 + 1] - h1);
            }
        }

        // ---- PV: o += P * V  (V^T frags via ldmatrix.trans) ----
        auto pv_pass = [&](uint32_t (*pf)[4], uint32_t vbase) {
#pragma unroll
            for (int c = 0; c < 4; ++c) {
                uint32_t bf[8][2];
#pragma unroll
                for (int db = 0; db < 4; ++db) {
                    uint32_t addr = vbase +
                        (uint32_t)((c * 16 + t_row) * SR2 + db * 16 + t_col) * 2;
                    ldmat4t(bf[2 * db][0], bf[2 * db][1],
                            bf[2 * db + 1][0], bf[2 * db + 1][1], addr);
                }
#pragma unroll
                for (int j = 0; j < 8; ++j) mma16816(o[j], pf[c], bf[j]);
            }
        };
        pv_pass(phi, kb + 18432);    // Ph*Vh
        pv_pass(phi, kb + 27648);    // Ph*Vl
        pv_pass(plo, kb + 18432);    // Pl*Vh

        __syncthreads();   // tile buffer fully consumed before reuse
    }

    // ---- epilogue: normalize, split to bf16, write ctx [Ch|Ch|Cl] ----
    l0 += __shfl_xor_sync(0xffffffffu, l0, 1);
    l0 += __shfl_xor_sync(0xffffffffu, l0, 2);
    l1 += __shfl_xor_sync(0xffffffffu, l1, 1);
    l1 += __shfl_xor_sync(0xffffffffu, l1, 2);
    const float i0 = 1.f / l0, i1 = 1.f / l1;

    const size_t grow0 = (size_t)b * S_ + qbase + 16 * wid + (lane >> 2);
    __nv_bfloat16* p0 = g_Cs + grow0 * K3 + h * HD_;
    __nv_bfloat16* p1 = g_Cs + (grow0 + 8) * K3 + h * HD_;
#pragma unroll
    for (int j = 0; j < 8; ++j) {
        const int cc = j * 8 + (lane & 3) * 2;
        __nv_bfloat162 hp, lp;
        split2(o[j][0] * i0, o[j][1] * i0, hp, lp);
        *(__nv_bfloat162*)(p0 + cc)          = hp;
        *(__nv_bfloat162*)(p0 + D_ + cc)     = hp;
        *(__nv_bfloat162*)(p0 + 2 * D_ + cc) = lp;
        split2(o[j][2] * i1, o[j][3] * i1, hp, lp);
        *(__nv_bfloat162*)(p1 + cc)          = hp;
        *(__nv_bfloat162*)(p1 + D_ + cc)     = hp;
        *(__nv_bfloat162*)(p1 + 2 * D_ + cc) = lp;
    }
}

// ---------------------------------------------------------------------------
extern "C" void kernel_launch(void* const* d_in, const int* in_sizes, int n_in,
                              void* d_out, int out_size) {
    const float* x      = (const float*)d_in[0];
    const float* qkv_w  = (const float*)d_in[1];
    const float* qkv_b  = (const float*)d_in[2];
    const float* proj_w = (const float*)d_in[3];
    const float* proj_b = (const float*)d_in[4];
    float* out          = (float*)d_out;

    cudaFuncSetAttribute(qkv_mma_kernel,
                         cudaFuncAttributeMaxDynamicSharedMemorySize, GEMM_SMEM);
    cudaFuncSetAttribute(proj_mma_kernel,
                         cudaFuncAttributeMaxDynamicSharedMemorySize, GEMM_SMEM);
    cudaFuncSetAttribute(flash_mma_kernel,
                         cudaFuncAttributeMaxDynamicSharedMemorySize, FLASH_SMEM);

    __nv_bfloat16 *xs, *wq3, *wp3;
    cudaGetSymbolAddress((void**)&xs,  g_Xs);
    cudaGetSymbolAddress((void**)&wq3, g_Wq3);
    cudaGetSymbolAddress((void**)&wp3, g_Wp3);

    split_kernel<<<1024, 256>>>(x,      xs,  MTOT * D_ / 4, 0);  // A-side
    split_kernel<<<512,  256>>>(qkv_w,  wq3, N3 * D_ / 4,  1);   // B-side
    split_kernel<<<256,  256>>>(proj_w, wp3, D_ * D_ / 4,  1);   // B-side

    dim3 g1(N3 / 128, MTOT / 128);     // (24, 64)
    qkv_mma_kernel<<<g1, 256, GEMM_SMEM>>>(qkv_b);

    dim3 g2(S_ / 128, H_, B_);         // (16, 16, 4)
    flash_mma_kernel<<<g2, 256, FLASH_SMEM>>>();

    dim3 g3(D_ / 128, MTOT / 128);     // (8, 64)
    proj_mma_kernel<<<g3, 256, GEMM_SMEM>>>(proj_b, out);
}